// round 3
// baseline (speedup 1.0000x reference)
#include <cuda_runtime.h>

// Per-box preprocessed params: cx, cy, cos, sin, hx, hy, pad, pad  (8 floats)
#define MAXB 8192
__device__ float g_params[MAXB * 8];

__global__ void prep_kernel(const float* __restrict__ boxes, int nb) {
    int i = blockIdx.x * blockDim.x + threadIdx.x;
    if (i >= nb) return;
    float cx = boxes[i * 5 + 0];
    float cy = boxes[i * 5 + 1];
    float hx = boxes[i * 5 + 2] * 0.5f;
    float hy = boxes[i * 5 + 3] * 0.5f;
    float ang = boxes[i * 5 + 4];
    float s, c;
    sincosf(ang, &s, &c);
    float4* p = reinterpret_cast<float4*>(&g_params[i * 8]);
    p[0] = make_float4(cx, cy, c, s);
    p[1] = make_float4(hx, hy, 0.0f, 0.0f);
}

// 1-D GIoU of [-r1, r1] vs [t-r2, t+r2], t >= 0.
// g = inter/uni - (hull-uni)/hull = (inter*hull + uni*(uni-hull)) / (uni*hull)
__device__ __forceinline__ float giou1d_sym(float r1, float r2, float t) {
    float tp = t + r2;
    float tm = t - r2;
    float inter = fmaxf(fminf(r1, tp) - fmaxf(-r1, tm), 0.0f);
    float uni  = 2.0f * (r1 + r2) - inter;
    float hull = fmaxf(r1, tp) - fminf(-r1, tm);
    float num  = fmaf(uni, uni - hull, inter * hull);
    return num * __fdividef(1.0f, uni * hull);
}

#define TILE 64

__global__ __launch_bounds__(256) void pair_kernel(float* __restrict__ out, int nb) {
    // sp[0] = i-tile boxes, sp[1] = j-tile boxes; 8 floats each
    __shared__ float sp[2][TILE][8];

    const int i0 = blockIdx.y * TILE;
    const int j0 = blockIdx.x * TILE;
    const int tid = threadIdx.x;

    // Cooperative load: 2 tiles * 64 boxes * 2 float4 = 256 float4 loads, one per thread
    {
        int which = tid >> 7;          // 0 -> i tile, 1 -> j tile
        int slot  = (tid >> 1) & 63;   // box within tile
        int half  = tid & 1;           // which float4 of the 8-float record
        int gidx  = (which ? j0 : i0) + slot;
        float4 v = make_float4(0.0f, 0.0f, 1.0f, 0.0f);
        if (gidx < nb)
            v = reinterpret_cast<const float4*>(g_params)[gidx * 2 + half];
        reinterpret_cast<float4*>(&sp[which][slot][0])[half] = v;
    }
    __syncthreads();

    const int tx = tid & 15;   // j sub-tile (4 boxes each)
    const int ty = tid >> 4;   // i sub-tile (4 boxes each)
    const int ib = ty * 4;
    const int jb = tx * 4;

    // Hoist the 4 j-box params into registers
    float cxj[4], cyj[4], cj[4], sj[4], hxj[4], hyj[4];
#pragma unroll
    for (int jj = 0; jj < 4; jj++) {
        const float* q = &sp[1][jb + jj][0];
        cxj[jj] = q[0]; cyj[jj] = q[1];
        cj[jj]  = q[2]; sj[jj]  = q[3];
        hxj[jj] = q[4]; hyj[jj] = q[5];
    }

#pragma unroll
    for (int ii = 0; ii < 4; ii++) {
        const float* p = &sp[0][ib + ii][0];
        const float cxi = p[0], cyi = p[1];
        const float ci  = p[2], si  = p[3];
        const float hxi = p[4], hyi = p[5];
        const int gi = i0 + ib + ii;

        float4 res;
        float* resf = &res.x;
#pragma unroll
        for (int jj = 0; jj < 4; jj++) {
            const float dx = cxj[jj] - cxi;
            const float dy = cyj[jj] - cyi;
            // cos/sin of angle difference
            const float cd = fmaf(ci, cj[jj], si * sj[jj]);
            const float sd = fmaf(si, cj[jj], -(ci * sj[jj]));
            const float A  = fabsf(cd);
            const float Bb = fabsf(sd);
            // center-delta projected on the 4 unit axes
            const float q1 = fabsf(fmaf(dx, ci, -(dy * si)));       // n1_i = (ci,-si)
            const float q2 = fabsf(fmaf(dx, si, dy * ci));          // n2_i = (si, ci)
            const float q3 = fabsf(fmaf(dx, cj[jj], -(dy * sj[jj])));
            const float q4 = fabsf(fmaf(dx, sj[jj], dy * cj[jj]));
            // other-box radii on each axis
            const float r21 = fmaf(hxj[jj], A,  hyj[jj] * Bb);
            const float r22 = fmaf(hxj[jj], Bb, hyj[jj] * A);
            const float r23 = fmaf(hxi,     A,  hyi * Bb);
            const float r24 = fmaf(hxi,     Bb, hyi * A);

            float g1 = giou1d_sym(hxi,     r21, q1);
            float g2 = giou1d_sym(hyi,     r22, q2);
            float g3 = giou1d_sym(hxj[jj], r23, q3);
            float g4 = giou1d_sym(hyj[jj], r24, q4);

            float g = fminf(fminf(g1, g2), fminf(g3, g4));
            g = fmaxf(g, 0.0f);
            const int gj = j0 + jb + jj;
            if (gi == gj) g = 0.0f;
            resf[jj] = g;
        }

        const int gjbase = j0 + jb;
        if (gi < nb && gjbase + 3 < nb) {
            *reinterpret_cast<float4*>(&out[(size_t)gi * nb + gjbase]) = res;
        } else if (gi < nb) {
#pragma unroll
            for (int jj = 0; jj < 4; jj++)
                if (gjbase + jj < nb) out[(size_t)gi * nb + gjbase + jj] = resf[jj];
        }
    }
}

extern "C" void kernel_launch(void* const* d_in, const int* in_sizes, int n_in,
                              void* d_out, int out_size) {
    const float* boxes = (const float*)d_in[0];
    float* out = (float*)d_out;
    const int nb = in_sizes[0] / 5;

    prep_kernel<<<(nb + 255) / 256, 256>>>(boxes, nb);

    dim3 grid((nb + TILE - 1) / TILE, (nb + TILE - 1) / TILE);
    pair_kernel<<<grid, 256>>>(out, nb);
}